// round 15
// baseline (speedup 1.0000x reference)
#include <cuda_runtime.h>
#include <cuda_bf16.h>
#include <math.h>
#include <stdint.h>

// Problem constants
#define BATCH 1024
#define DDIM  64
#define MNUM  3
#define CNUM  16384
#define NBR   2

// Persistent GEMM: 296 workers (2/SM x 148). Unit = one 128-c x 128-b tile.
// Unit u: z = u>>10, bT = (u>>7)&7, cG = u&127. Column (z,bT) = u>>7 shares B.
// A loaded as fp32 (cp.async, double-buffered staging), converted in-smem to
// bf16 pre-scaled by 0.5/conc, so MMA output = dot/(2*conc).
#define TC 128
#define TB 128
#define NUNITS   6144
#define NWORKERS 296
#define UBASE    20
#define UREM     224
#define PITCH  144          // bf16 tile row pitch (64 bf16 + 8 pad)
#define PITCHF 272          // fp32 staging row pitch (64 fp32 + 4 pad)

// smem layout (bytes)
#define SMEM_F0    0                      // 34816 fp32 A staging buf 0
#define SMEM_F1    34816                  // 34816 fp32 A staging buf 1
#define SMEM_A     69632                  // 18432 bf16 A tile
#define SMEM_B     88064                  // 18432 bf16 B tile
#define SMEM_SACC  106496                 // 8 warps * 32 floats
#define SMEM_TOTAL 107520                 // x2 CTA = 210KB/SM (fits 228KB)

// finalize grid
#define FIN_BLOCKS 24
#define FIN_THREADS 256

typedef unsigned long long u64;

__device__ __forceinline__ u64 splat2(float v) {
    u64 r; asm("mov.b64 %0, {%1, %1};" : "=l"(r) : "f"(v)); return r;
}
__device__ __forceinline__ u64 pack2(float lo, float hi) {
    u64 r; asm("mov.b64 %0, {%1, %2};" : "=l"(r) : "f"(lo), "f"(hi)); return r;
}
__device__ __forceinline__ u64 ffma2(u64 a, u64 b, u64 c) {
    u64 d; asm("fma.rn.f32x2 %0, %1, %2, %3;" : "=l"(d) : "l"(a), "l"(b), "l"(c)); return d;
}
__device__ __forceinline__ u64 fadd2(u64 a, u64 b) {
    u64 d; asm("add.rn.f32x2 %0, %1, %2;" : "=l"(d) : "l"(a), "l"(b)); return d;
}
__device__ __forceinline__ uint32_t bf2(float lo, float hi) {
    uint32_t r; asm("cvt.rn.bf16x2.f32 %0, %1, %2;" : "=r"(r) : "f"(hi), "f"(lo)); return r;
}
__device__ __forceinline__ uint32_t smem_u32(const void* p) {
    uint32_t a;
    asm("{ .reg .u64 t; cvta.to.shared.u64 t, %1; cvt.u32.u64 %0, t; }" : "=r"(a) : "l"(p));
    return a;
}
__device__ __forceinline__ u64 shfl_xor2(u64 v, int mask) {
    uint32_t lo = (uint32_t)v, hi = (uint32_t)(v >> 32);
    lo = __shfl_xor_sync(0xffffffffu, lo, mask);
    hi = __shfl_xor_sync(0xffffffffu, hi, mask);
    return ((u64)hi << 32) | (u64)lo;
}
__device__ __forceinline__ void cp16(uint32_t dst, const void* src) {
    asm volatile("cp.async.cg.shared.global [%0], [%1], 16;" :: "r"(dst), "l"(src));
}
#define CP_COMMIT() asm volatile("cp.async.commit_group;" ::: "memory")
#define CP_WAIT0()  asm volatile("cp.async.wait_group 0;" ::: "memory")

#define LDSM4(r, addr)                                                              \
    asm volatile("ldmatrix.sync.aligned.m8n8.x4.shared.b16 {%0,%1,%2,%3}, [%4];"    \
        : "=r"((r)[0]), "=r"((r)[1]), "=r"((r)[2]), "=r"((r)[3]) : "r"(addr))

#define MMA16816(c, a, b)                                                           \
    asm volatile("mma.sync.aligned.m16n8k16.row.col.f32.bf16.bf16.f32 "             \
        "{%0,%1,%2,%3}, {%4,%5,%6,%7}, {%8,%9}, {%0,%1,%2,%3};"                     \
        : "+f"((c)[0]), "+f"((c)[1]), "+f"((c)[2]), "+f"((c)[3])                    \
        : "r"((a)[0]), "r"((a)[1]), "r"((a)[2]), "r"((a)[3]), "r"((b)[0]), "r"((b)[1]))

// bf16 features. branch 0 uses feats_I, branch 1 uses feats.
__device__ __align__(16) __nv_bfloat16 g_featb[NBR * BATCH * DDIM];
// 0.5/conc table: [branch][m][c] = z*16384 + c
__device__ float g_invc[NBR * MNUM * CNUM];

// Scratch: per-(branch,m,b) sum of exp(logit). 6144 floats.
__device__ float g_S[NBR * MNUM * BATCH];
__device__ float g_part[FIN_BLOCKS];
__device__ unsigned int g_done;

#define INVC_N (NBR * MNUM * CNUM)         // 98304
#define FEAT4  (BATCH * (DDIM / 4))        // 16384 float4 per branch
#define CONV_N (INVC_N + 2 * FEAT4)        // 131072

__global__ void convert_kernel(const float* __restrict__ f,   const float* __restrict__ fI,
                               const float* __restrict__ conc, const float* __restrict__ concI)
{
    int idx = blockIdx.x * blockDim.x + threadIdx.x;
    if (idx == 0) g_done = 0;                         // reset ticket each replay
    if (idx < NBR * MNUM * BATCH) g_S[idx] = 0.0f;    // init merged here
    if (idx < INVC_N) {
        int branch = idx / (MNUM * CNUM);
        int r = idx - branch * (MNUM * CNUM);
        g_invc[idx] = __fdividef(0.5f, (branch ? concI : conc)[r]);
    } else if (idx < CONV_N) {
        int t = idx - INVC_N;
        int branch = t / FEAT4, r = t - branch * FEAT4;
        const float4 v = ((const float4*)(branch ? f : fI))[r];   // branch0 -> feats_I
        uint2 p; p.x = bf2(v.x, v.y); p.y = bf2(v.z, v.w);
        ((uint2*)g_featb)[branch * FEAT4 + r] = p;
    }
}

// Persistent: worker = blockIdx.x owns a contiguous unit range (mostly one B col).
__global__ __launch_bounds__(256, 2)
void mma_exp_kernel(const float* __restrict__ cen, const float* __restrict__ cenI)
{
    extern __shared__ char smem[];
    const uint32_t sb = smem_u32(smem);
    const int tid = threadIdx.x;
    const int wid = tid >> 5, lane = tid & 31;
    const int wc = wid >> 2, wb = wid & 3;          // warp grid 2(c) x 4(b)

    const int w = blockIdx.x;
    const int cnt = UBASE + (w < UREM);
    const int start = w * UBASE + (w < UREM ? w : UREM);

    const uint32_t aOff = (64 * wc + (lane & 15)) * PITCH + ((lane & 16) ? 16 : 0);
    const uint32_t bAddr = sb + SMEM_B + (32 * wb + (lane & 7) + ((lane & 16) ? 8 : 0)) * PITCH
                              + ((lane & 8) ? 16 : 0);
    const u64 k3 = splat2(1.0f/6.0f), k2 = splat2(0.5f), one = splat2(1.0f);
    float* sacc = (float*)(smem + SMEM_SACC);

    // conversion mapping: 2 threads per row
    const int crow = tid >> 1, chalf = tid & 1;
    const uint32_t cvtSrcOff = crow * PITCHF + chalf * 128;   // within staging buf
    char* cvtDst = smem + SMEM_A + crow * PITCH + chalf * 64;

    u64 colsum[4];
    #pragma unroll
    for (int j = 0; j < 4; j++) colsum[j] = 0ULL;

    // issue B(col of first unit) + fp32 A(first unit) into staging 0
    {
        int u0 = start, col0 = u0 >> 7;
        const uint4* gB = (const uint4*)(g_featb +
            ((size_t)(col0 >= 24) * BATCH + (size_t)(col0 & 7) * TB) * DDIM);
        const float* cp = (u0 >> 10) >= MNUM ? cenI : cen;
        int mm = (u0 >> 10) >= MNUM ? (u0 >> 10) - MNUM : (u0 >> 10);
        const uint4* gA = (const uint4*)(cp + ((size_t)mm * CNUM + (size_t)(u0 & 127) * TC) * DDIM);
        #pragma unroll
        for (int it = 0; it < 4; it++) {
            int q = tid + 256 * it;
            int row = q >> 3, seg = q & 7;
            cp16(sb + SMEM_B + row * PITCH + seg * 16, gB + q);
        }
        #pragma unroll
        for (int it = 0; it < 8; it++) {              // 2048 uint4 fp32
            int q = tid + 256 * it;
            int row = q >> 4, seg = q & 15;
            cp16(sb + SMEM_F0 + row * PITCHF + seg * 16, gA + q);
        }
        CP_COMMIT();
    }

    int prevCol = start >> 7;
    int buf = 0;

    for (int k = 0; k < cnt; k++) {
        const int u = start + k;
        const int col = u >> 7;
        const int z = u >> 10;

        CP_WAIT0();                                  // fp32 A(u) (and B on k==0) arrived
        __syncthreads();                             // all warps past prior iter entirely

        if (col != prevCol) {                        // flush old column, load new B
            #pragma unroll
            for (int mask = 4; mask <= 16; mask <<= 1)
                #pragma unroll
                for (int j = 0; j < 4; j++)
                    colsum[j] = fadd2(colsum[j], shfl_xor2(colsum[j], mask));
            if (lane < 4) {
                #pragma unroll
                for (int j = 0; j < 4; j++) {
                    float2 v; v.x = __uint_as_float((uint32_t)colsum[j]);
                    v.y = __uint_as_float((uint32_t)(colsum[j] >> 32));
                    *(float2*)&sacc[wid * 32 + 8 * j + 2 * lane] = v;
                }
            }
            #pragma unroll
            for (int j = 0; j < 4; j++) colsum[j] = 0ULL;
            __syncthreads();
            if (tid < TB) {
                int wb2 = tid >> 5, lc = tid & 31;
                float s = sacc[wb2 * 32 + lc] + sacc[(wb2 + 4) * 32 + lc];
                atomicAdd(&g_S[prevCol * TB + tid], s);
            }
            __syncthreads();                         // B safe to overwrite
            const uint4* gB = (const uint4*)(g_featb +
                ((size_t)(col >= 24) * BATCH + (size_t)(col & 7) * TB) * DDIM);
            #pragma unroll
            for (int it = 0; it < 4; it++) {
                int q = tid + 256 * it;
                int row = q >> 3, seg = q & 7;
                cp16(sb + SMEM_B + row * PITCH + seg * 16, gB + q);
            }
            CP_COMMIT();
            CP_WAIT0();
            __syncthreads();
            prevCol = col;
        }

        if (k + 1 < cnt) {                           // prefetch fp32 A(u+1) into other buf
            int un = u + 1;
            const float* cp = (un >> 10) >= MNUM ? cenI : cen;
            int mm = (un >> 10) >= MNUM ? (un >> 10) - MNUM : (un >> 10);
            const uint4* gAn = (const uint4*)(cp +
                ((size_t)mm * CNUM + (size_t)(un & 127) * TC) * DDIM);
            uint32_t dstF = sb + ((buf ^ 1) ? SMEM_F1 : SMEM_F0);
            #pragma unroll
            for (int it = 0; it < 8; it++) {
                int q = tid + 256 * it;
                int row = q >> 4, seg = q & 15;
                cp16(dstF + row * PITCHF + seg * 16, gAn + q);
            }
            CP_COMMIT();
        }

        // ---- convert fp32 staging -> bf16 A tile, pre-scaled by 0.5/conc ----
        {
            const char* src = smem + (buf ? SMEM_F1 : SMEM_F0) + cvtSrcOff;
            const float s = g_invc[z * CNUM + (u & 127) * TC + crow];
            #pragma unroll
            for (int i = 0; i < 4; i++) {
                float4 va = *(const float4*)(src + i * 32);
                float4 vb = *(const float4*)(src + i * 32 + 16);
                uint4 o;
                o.x = bf2(va.x * s, va.y * s);
                o.y = bf2(va.z * s, va.w * s);
                o.z = bf2(vb.x * s, vb.y * s);
                o.w = bf2(vb.z * s, vb.w * s);
                *(uint4*)(cvtDst + i * 16) = o;
            }
        }
        __syncthreads();                             // bf16 A ready for LDSM

        const uint32_t aAddr = sb + SMEM_A + aOff;

        // ---- GEMM: warp tile 64x32, 4 k-steps of 16 ----
        float c[4][4][4];
        #pragma unroll
        for (int i = 0; i < 4; i++)
            #pragma unroll
            for (int j = 0; j < 4; j++)
                #pragma unroll
                for (int r = 0; r < 4; r++) c[i][j][r] = 0.0f;

        #pragma unroll
        for (int ks = 0; ks < 4; ks++) {
            uint32_t a[4][4];
            #pragma unroll
            for (int i = 0; i < 4; i++)
                LDSM4(a[i], aAddr + i * (16 * PITCH) + ks * 32);
            uint32_t b0[4], b1[4];
            LDSM4(b0, bAddr + ks * 32);
            LDSM4(b1, bAddr + 16 * PITCH + ks * 32);
            uint32_t bb[4][2] = {{b0[0], b0[1]}, {b0[2], b0[3]}, {b1[0], b1[1]}, {b1[2], b1[3]}};
            #pragma unroll
            for (int i = 0; i < 4; i++)
                #pragma unroll
                for (int j = 0; j < 4; j++)
                    MMA16816(c[i][j], a[i], bb[j]);
        }

        // ---- epilogue: x = dot/(2 conc); exp = (e^x)^2, deg-3 Taylor, packed ----
        #pragma unroll
        for (int i = 0; i < 4; i++)
            #pragma unroll
            for (int j = 0; j < 4; j++)
                #pragma unroll
                for (int h = 0; h < 2; h++) {
                    u64 x = pack2(c[i][j][2 * h], c[i][j][2 * h + 1]);
                    u64 p = ffma2(x, k3, k2);
                    p = ffma2(x, p, one);
                    p = ffma2(x, p, one);
                    colsum[j] = ffma2(p, p, colsum[j]);   // += e^{dot/conc}
                }

        buf ^= 1;
    }

    // final flush
    #pragma unroll
    for (int mask = 4; mask <= 16; mask <<= 1)
        #pragma unroll
        for (int j = 0; j < 4; j++)
            colsum[j] = fadd2(colsum[j], shfl_xor2(colsum[j], mask));
    if (lane < 4) {
        #pragma unroll
        for (int j = 0; j < 4; j++) {
            float2 v; v.x = __uint_as_float((uint32_t)colsum[j]);
            v.y = __uint_as_float((uint32_t)(colsum[j] >> 32));
            *(float2*)&sacc[wid * 32 + 8 * j + 2 * lane] = v;
        }
    }
    __syncthreads();
    if (tid < TB) {
        int wb2 = tid >> 5, lc = tid & 31;
        float s = sacc[wb2 * 32 + lc] + sacc[(wb2 + 4) * 32 + lc];
        atomicAdd(&g_S[prevCol * TB + tid], s);
    }
}

// Finalize: 24 blocks x 256 threads, one (branch,m,b) per thread; last block
// sums the 24 partials in fixed order and writes the scalar.
__global__ void finalize_kernel(const float* __restrict__ cen,  const float* __restrict__ cenI,
                                const float* __restrict__ f,    const float* __restrict__ fI,
                                const float* __restrict__ conc, const float* __restrict__ concI,
                                const int* __restrict__ lab,    const int* __restrict__ labI,
                                const int* __restrict__ lb,     float* __restrict__ out)
{
    __shared__ float sred[FIN_THREADS];
    __shared__ bool last;
    const int tid = threadIdx.x;
    const int idx = blockIdx.x * FIN_THREADS + tid;   // 0..6143

    int branch = idx / (MNUM * BATCH);
    int r = idx - branch * MNUM * BATCH;
    int m = r / BATCH;
    int b = r - m * BATCH;

    const float* cenP  = branch ? cenI  : cen;
    const float* featP = branch ? f     : fI;
    const float* concP = branch ? concI : conc;
    const int*   labP  = branch ? labI  : lab;

    int cidx = labP[m * BATCH + b];
    const float4* cr = (const float4*)(cenP + ((size_t)(m * CNUM) + cidx) * DDIM);
    const float4* fr = (const float4*)(featP + (size_t)b * DDIM);
    float dot = 0.0f;
    #pragma unroll
    for (int d = 0; d < 16; d++) {
        float4 a = cr[d];
        float4 w = fr[d];
        dot += a.x * w.x + a.y * w.y + a.z * w.z + a.w * w.w;
    }
    float logit = dot / concP[m * CNUM + cidx];
    sred[tid] = logit - logf(g_S[idx]);     // log(pos/sum) = logit_pos - log(S)
    __syncthreads();
    #pragma unroll
    for (int s = FIN_THREADS / 2; s > 0; s >>= 1) {
        if (tid < s) sred[tid] += sred[tid + s];
        __syncthreads();
    }
    if (tid == 0) {
        g_part[blockIdx.x] = sred[0];
        __threadfence();
        unsigned int t = atomicAdd(&g_done, 1u);
        last = (t == FIN_BLOCKS - 1);
    }
    __syncthreads();
    if (last && tid == 0) {
        float s = 0.0f;
        #pragma unroll
        for (int i = 0; i < FIN_BLOCKS; i++) s += g_part[i];
        float scale = -(float)lb[0] / (2.0f * (float)BATCH * (float)MNUM);
        out[0] = scale * s;
    }
}

extern "C" void kernel_launch(void* const* d_in, const int* in_sizes, int n_in,
                              void* d_out, int out_size)
{
    const float* f     = (const float*)d_in[0];
    const float* fI    = (const float*)d_in[1];
    const float* cen   = (const float*)d_in[2];
    const float* cenI  = (const float*)d_in[3];
    const float* conc  = (const float*)d_in[4];
    const float* concI = (const float*)d_in[5];
    const int*   lab   = (const int*)d_in[6];
    const int*   labI  = (const int*)d_in[7];
    const int*   lb    = (const int*)d_in[8];
    float* out = (float*)d_out;

    cudaFuncSetAttribute(mma_exp_kernel,
                         cudaFuncAttributeMaxDynamicSharedMemorySize, SMEM_TOTAL);

    convert_kernel<<<(CONV_N + 255) / 256, 256>>>(f, fI, conc, concI);
    mma_exp_kernel<<<NWORKERS, 256, SMEM_TOTAL>>>(cen, cenI);
    finalize_kernel<<<FIN_BLOCKS, FIN_THREADS>>>(cen, cenI, f, fI, conc, concI, lab, labI, lb, out);
}

// round 17
// speedup vs baseline: 1.3699x; 1.3699x over previous
#include <cuda_runtime.h>
#include <cuda_bf16.h>
#include <math.h>
#include <stdint.h>

// Problem constants
#define BATCH 1024
#define DDIM  64
#define MNUM  3
#define CNUM  16384
#define NBR   2

// Persistent GEMM: 296 workers (2/SM x 148). Units = one 128-c x 128-b tile.
// Unit u: z = u>>10, bT = (u>>7)&7, cG = u&127. Column (z,bT) = u>>7 shares B.
// A pre-scaled by 0.5/conc during convert, so MMA output = dot/(2*conc).
#define TC 128
#define TB 128
#define NUNITS   6144
#define NWORKERS 296
#define UBASE    20
#define UREM     224
#define PITCH 144          // smem row pitch bytes (64 bf16 + 8 pad)

// smem layout (bytes)
#define SMEM_A0    0                      // 18432
#define SMEM_A1    18432                  // 18432
#define SMEM_B     36864                  // 18432
#define SMEM_SACC  55296                  // 8 warps * 32 floats
#define SMEM_TOTAL 56320

// finalize grid
#define FIN_BLOCKS 24
#define FIN_THREADS 256

typedef unsigned long long u64;

__device__ __forceinline__ u64 splat2(float v) {
    u64 r; asm("mov.b64 %0, {%1, %1};" : "=l"(r) : "f"(v)); return r;
}
__device__ __forceinline__ u64 pack2(float lo, float hi) {
    u64 r; asm("mov.b64 %0, {%1, %2};" : "=l"(r) : "f"(lo), "f"(hi)); return r;
}
__device__ __forceinline__ u64 ffma2(u64 a, u64 b, u64 c) {
    u64 d; asm("fma.rn.f32x2 %0, %1, %2, %3;" : "=l"(d) : "l"(a), "l"(b), "l"(c)); return d;
}
__device__ __forceinline__ u64 fadd2(u64 a, u64 b) {
    u64 d; asm("add.rn.f32x2 %0, %1, %2;" : "=l"(d) : "l"(a), "l"(b)); return d;
}
__device__ __forceinline__ uint32_t bf2(float lo, float hi) {
    uint32_t r; asm("cvt.rn.bf16x2.f32 %0, %1, %2;" : "=r"(r) : "f"(hi), "f"(lo)); return r;
}
__device__ __forceinline__ uint32_t smem_u32(const void* p) {
    uint32_t a;
    asm("{ .reg .u64 t; cvta.to.shared.u64 t, %1; cvt.u32.u64 %0, t; }" : "=r"(a) : "l"(p));
    return a;
}
__device__ __forceinline__ u64 shfl_xor2(u64 v, int mask) {
    uint32_t lo = (uint32_t)v, hi = (uint32_t)(v >> 32);
    lo = __shfl_xor_sync(0xffffffffu, lo, mask);
    hi = __shfl_xor_sync(0xffffffffu, hi, mask);
    return ((u64)hi << 32) | (u64)lo;
}
__device__ __forceinline__ void cp16(uint32_t dst, const void* src) {
    asm volatile("cp.async.cg.shared.global [%0], [%1], 16;" :: "r"(dst), "l"(src));
}
#define CP_COMMIT() asm volatile("cp.async.commit_group;" ::: "memory")
#define CP_WAIT0()  asm volatile("cp.async.wait_group 0;" ::: "memory")

#define LDSM4(r, addr)                                                              \
    asm volatile("ldmatrix.sync.aligned.m8n8.x4.shared.b16 {%0,%1,%2,%3}, [%4];"    \
        : "=r"((r)[0]), "=r"((r)[1]), "=r"((r)[2]), "=r"((r)[3]) : "r"(addr))

#define MMA16816(c, a, b)                                                           \
    asm volatile("mma.sync.aligned.m16n8k16.row.col.f32.bf16.bf16.f32 "             \
        "{%0,%1,%2,%3}, {%4,%5,%6,%7}, {%8,%9}, {%0,%1,%2,%3};"                     \
        : "+f"((c)[0]), "+f"((c)[1]), "+f"((c)[2]), "+f"((c)[3])                    \
        : "r"((a)[0]), "r"((a)[1]), "r"((a)[2]), "r"((a)[3]), "r"((b)[0]), "r"((b)[1]))

// bf16 copies. g_cenb rows are pre-scaled by 0.5/conc (branch-matched).
// branch 0 uses (cen, conc, feats_I), branch 1 (cen_I, conc_I, feats).
__device__ __align__(16) __nv_bfloat16 g_cenb[NBR * MNUM * CNUM * DDIM];
__device__ __align__(16) __nv_bfloat16 g_featb[NBR * BATCH * DDIM];

// Scratch: per-(branch,m,b) sum of exp(logit) and positive logit. 6144 floats each.
__device__ float g_S[NBR * MNUM * BATCH];
__device__ float g_pos[NBR * MNUM * BATCH];
__device__ float g_part[FIN_BLOCKS];
__device__ unsigned int g_done;

#define CEN4  (MNUM * CNUM * (DDIM / 4))   // float4s per branch of centroids
#define FEAT4 (BATCH * (DDIM / 4))

__global__ void convert_kernel(const float* __restrict__ cen, const float* __restrict__ cenI,
                               const float* __restrict__ f,   const float* __restrict__ fI,
                               const float* __restrict__ conc, const float* __restrict__ concI,
                               const int* __restrict__ lab,   const int* __restrict__ labI)
{
    int idx = blockIdx.x * blockDim.x + threadIdx.x;
    if (idx == 0) g_done = 0;                         // reset ticket each replay
    if (idx < NBR * MNUM * BATCH) {                   // init + positive logit (input-only)
        g_S[idx] = 0.0f;
        int branch = idx / (MNUM * BATCH);
        int r = idx - branch * MNUM * BATCH;
        int m = r / BATCH;
        int b = r - m * BATCH;
        const float* cenP  = branch ? cenI  : cen;
        const float* featP = branch ? f     : fI;
        const float* concP = branch ? concI : conc;
        const int*   labP  = branch ? labI  : lab;
        int cidx = labP[m * BATCH + b];
        const float4* cr = (const float4*)(cenP + ((size_t)(m * CNUM) + cidx) * DDIM);
        const float4* fr = (const float4*)(featP + (size_t)b * DDIM);
        float dot = 0.0f;
        #pragma unroll
        for (int d = 0; d < 16; d++) {
            float4 a = cr[d];
            float4 w = fr[d];
            dot += a.x * w.x + a.y * w.y + a.z * w.z + a.w * w.w;
        }
        g_pos[idx] = dot / concP[m * CNUM + cidx];
    }
    if (idx < 2 * CEN4) {
        int branch = idx / CEN4, r = idx - branch * CEN4;
        const float4 v = ((const float4*)(branch ? cenI : cen))[r];
        int row = r >> 4;                             // m*CNUM + c within branch
        float s = __fdividef(0.5f, (branch ? concI : conc)[row]);
        uint2 p; p.x = bf2(v.x * s, v.y * s); p.y = bf2(v.z * s, v.w * s);
        ((uint2*)g_cenb)[branch * CEN4 + r] = p;
    } else if (idx < 2 * CEN4 + 2 * FEAT4) {
        int t = idx - 2 * CEN4;
        int branch = t / FEAT4, r = t - branch * FEAT4;
        const float4 v = ((const float4*)(branch ? f : fI))[r];   // branch0 -> feats_I
        uint2 p; p.x = bf2(v.x, v.y); p.y = bf2(v.z, v.w);
        ((uint2*)g_featb)[branch * FEAT4 + r] = p;
    }
}

// Persistent: worker = blockIdx.x owns a contiguous unit range (mostly one B col).
__global__ __launch_bounds__(256, 2)
void mma_exp_kernel()
{
    extern __shared__ char smem[];
    const uint32_t sb = smem_u32(smem);
    const int tid = threadIdx.x;
    const int wid = tid >> 5, lane = tid & 31;
    const int wc = wid >> 2, wb = wid & 3;          // warp grid 2(c) x 4(b)

    const int w = blockIdx.x;
    const int cnt = UBASE + (w < UREM);
    const int start = w * UBASE + (w < UREM ? w : UREM);

    const uint32_t aOff = (64 * wc + (lane & 15)) * PITCH + ((lane & 16) ? 16 : 0);
    const uint32_t bAddr = sb + SMEM_B + (32 * wb + (lane & 7) + ((lane & 16) ? 8 : 0)) * PITCH
                              + ((lane & 8) ? 16 : 0);
    const u64 k3 = splat2(1.0f/6.0f), k2 = splat2(0.5f), one = splat2(1.0f);
    float* sacc = (float*)(smem + SMEM_SACC);

    u64 colsum[4];
    #pragma unroll
    for (int j = 0; j < 4; j++) colsum[j] = 0ULL;

    // issue B(col of first unit) + A(first unit) into buffer 0
    {
        int u0 = start, col0 = u0 >> 7;
        const uint4* gB = (const uint4*)(g_featb +
            ((size_t)(col0 >= 24) * BATCH + (size_t)(col0 & 7) * TB) * DDIM);
        const uint4* gA = (const uint4*)(g_cenb +
            (((size_t)(u0 >> 10)) * CNUM + (size_t)(u0 & 127) * TC) * DDIM);
        #pragma unroll
        for (int it = 0; it < 4; it++) {
            int q = tid + 256 * it;
            int row = q >> 3, seg = q & 7;
            cp16(sb + SMEM_B + row * PITCH + seg * 16, gB + q);
            cp16(sb + SMEM_A0 + row * PITCH + seg * 16, gA + q);
        }
        CP_COMMIT();
    }

    int prevCol = start >> 7;
    int buf = 0;

    for (int k = 0; k < cnt; k++) {
        const int u = start + k;
        const int col = u >> 7;

        CP_WAIT0();                                  // A(u) (and B on k==0) arrived
        __syncthreads();                             // all warps past prior buffer reads

        if (col != prevCol) {                        // flush old column, load new B
            #pragma unroll
            for (int mask = 4; mask <= 16; mask <<= 1)
                #pragma unroll
                for (int j = 0; j < 4; j++)
                    colsum[j] = fadd2(colsum[j], shfl_xor2(colsum[j], mask));
            if (lane < 4) {
                #pragma unroll
                for (int j = 0; j < 4; j++) {
                    float2 v; v.x = __uint_as_float((uint32_t)colsum[j]);
                    v.y = __uint_as_float((uint32_t)(colsum[j] >> 32));
                    *(float2*)&sacc[wid * 32 + 8 * j + 2 * lane] = v;
                }
            }
            #pragma unroll
            for (int j = 0; j < 4; j++) colsum[j] = 0ULL;
            __syncthreads();
            if (tid < TB) {
                int wb2 = tid >> 5, lc = tid & 31;
                float s = sacc[wb2 * 32 + lc] + sacc[(wb2 + 4) * 32 + lc];
                atomicAdd(&g_S[prevCol * TB + tid], s);
            }
            __syncthreads();                         // atomic reads done; B safe to overwrite
            const uint4* gB = (const uint4*)(g_featb +
                ((size_t)(col >= 24) * BATCH + (size_t)(col & 7) * TB) * DDIM);
            #pragma unroll
            for (int it = 0; it < 4; it++) {
                int q = tid + 256 * it;
                int row = q >> 3, seg = q & 7;
                cp16(sb + SMEM_B + row * PITCH + seg * 16, gB + q);
            }
            CP_COMMIT();
            CP_WAIT0();
            __syncthreads();
            prevCol = col;
        }

        if (k + 1 < cnt) {                           // prefetch A(u+1) into other buf
            int un = u + 1;
            const uint4* gAn = (const uint4*)(g_cenb +
                (((size_t)(un >> 10)) * CNUM + (size_t)(un & 127) * TC) * DDIM);
            uint32_t dstA = sb + ((buf ^ 1) ? SMEM_A1 : SMEM_A0);
            #pragma unroll
            for (int it = 0; it < 4; it++) {
                int q = tid + 256 * it;
                int row = q >> 3, seg = q & 7;
                cp16(dstA + row * PITCH + seg * 16, gAn + q);
            }
            CP_COMMIT();
        }

        const uint32_t aAddr = sb + (buf ? SMEM_A1 : SMEM_A0) + aOff;

        // ---- GEMM: warp tile 64x32, 4 k-steps of 16 ----
        float c[4][4][4];
        #pragma unroll
        for (int i = 0; i < 4; i++)
            #pragma unroll
            for (int j = 0; j < 4; j++)
                #pragma unroll
                for (int r = 0; r < 4; r++) c[i][j][r] = 0.0f;

        #pragma unroll
        for (int ks = 0; ks < 4; ks++) {
            uint32_t a[4][4];
            #pragma unroll
            for (int i = 0; i < 4; i++)
                LDSM4(a[i], aAddr + i * (16 * PITCH) + ks * 32);
            uint32_t b0[4], b1[4];
            LDSM4(b0, bAddr + ks * 32);
            LDSM4(b1, bAddr + 16 * PITCH + ks * 32);
            uint32_t bb[4][2] = {{b0[0], b0[1]}, {b0[2], b0[3]}, {b1[0], b1[1]}, {b1[2], b1[3]}};
            #pragma unroll
            for (int i = 0; i < 4; i++)
                #pragma unroll
                for (int j = 0; j < 4; j++)
                    MMA16816(c[i][j], a[i], bb[j]);
        }

        // ---- epilogue: x = dot/(2 conc); exp = (e^x)^2, deg-3 Taylor, packed ----
        #pragma unroll
        for (int i = 0; i < 4; i++)
            #pragma unroll
            for (int j = 0; j < 4; j++)
                #pragma unroll
                for (int h = 0; h < 2; h++) {
                    u64 x = pack2(c[i][j][2 * h], c[i][j][2 * h + 1]);
                    u64 p = ffma2(x, k3, k2);
                    p = ffma2(x, p, one);
                    p = ffma2(x, p, one);
                    colsum[j] = ffma2(p, p, colsum[j]);   // += e^{dot/conc}
                }

        buf ^= 1;
    }

    // final flush
    #pragma unroll
    for (int mask = 4; mask <= 16; mask <<= 1)
        #pragma unroll
        for (int j = 0; j < 4; j++)
            colsum[j] = fadd2(colsum[j], shfl_xor2(colsum[j], mask));
    if (lane < 4) {
        #pragma unroll
        for (int j = 0; j < 4; j++) {
            float2 v; v.x = __uint_as_float((uint32_t)colsum[j]);
            v.y = __uint_as_float((uint32_t)(colsum[j] >> 32));
            *(float2*)&sacc[wid * 32 + 8 * j + 2 * lane] = v;
        }
    }
    __syncthreads();
    if (tid < TB) {
        int wb2 = tid >> 5, lc = tid & 31;
        float s = sacc[wb2 * 32 + lc] + sacc[(wb2 + 4) * 32 + lc];
        atomicAdd(&g_S[prevCol * TB + tid], s);
    }
}

// Finalize: g_pos already computed; just log(S), reduce, scale.
__global__ void finalize_kernel(const int* __restrict__ lb, float* __restrict__ out)
{
    __shared__ float sred[FIN_THREADS];
    __shared__ bool last;
    const int tid = threadIdx.x;
    const int idx = blockIdx.x * FIN_THREADS + tid;   // 0..6143

    sred[tid] = g_pos[idx] - logf(g_S[idx]);   // log(pos/sum) = logit_pos - log(S)
    __syncthreads();
    #pragma unroll
    for (int s = FIN_THREADS / 2; s > 0; s >>= 1) {
        if (tid < s) sred[tid] += sred[tid + s];
        __syncthreads();
    }
    if (tid == 0) {
        g_part[blockIdx.x] = sred[0];
        __threadfence();
        unsigned int t = atomicAdd(&g_done, 1u);
        last = (t == FIN_BLOCKS - 1);
    }
    __syncthreads();
    if (last && tid == 0) {
        float s = 0.0f;
        #pragma unroll
        for (int i = 0; i < FIN_BLOCKS; i++) s += g_part[i];
        float scale = -(float)lb[0] / (2.0f * (float)BATCH * (float)MNUM);
        out[0] = scale * s;
    }
}

extern "C" void kernel_launch(void* const* d_in, const int* in_sizes, int n_in,
                              void* d_out, int out_size)
{
    const float* f     = (const float*)d_in[0];
    const float* fI    = (const float*)d_in[1];
    const float* cen   = (const float*)d_in[2];
    const float* cenI  = (const float*)d_in[3];
    const float* conc  = (const float*)d_in[4];
    const float* concI = (const float*)d_in[5];
    const int*   lab   = (const int*)d_in[6];
    const int*   labI  = (const int*)d_in[7];
    const int*   lb    = (const int*)d_in[8];
    float* out = (float*)d_out;

    cudaFuncSetAttribute(mma_exp_kernel,
                         cudaFuncAttributeMaxDynamicSharedMemorySize, SMEM_TOTAL);

    int convN = 2 * CEN4 + 2 * FEAT4;
    convert_kernel<<<(convN + 255) / 256, 256>>>(cen, cenI, f, fI, conc, concI, lab, labI);
    mma_exp_kernel<<<NWORKERS, 256, SMEM_TOTAL>>>();
    finalize_kernel<<<FIN_BLOCKS, FIN_THREADS>>>(lb, out);
}